// round 1
// baseline (speedup 1.0000x reference)
#include <cuda_runtime.h>

#define KC   512
#define DD   64
#define NN   2048
#define BB   64
#define TM   128
#define TN   128
#define NTHREADS 256
#define NBLOCKS  1024   // (BB*NN)/TM
#define PAD  4          // smem row pad -> stride 132 floats (16B aligned)

__device__ float g_w[KC];
__device__ float g_c2[KC];
__device__ float g_part[NBLOCKS];

// ---------------------------------------------------------------------------
// Prep: softmax(psi) -> g_w, ||c||^2 -> g_c2. One CTA of 512 threads.
// ---------------------------------------------------------------------------
__global__ void prep_kernel(const float* __restrict__ psi,
                            const float* __restrict__ centers) {
    __shared__ float sh[KC];
    int t = threadIdx.x;           // 0..511
    float p = psi[t];
    sh[t] = p;
    __syncthreads();
    #pragma unroll
    for (int s = 256; s > 0; s >>= 1) {
        if (t < s) sh[t] = fmaxf(sh[t], sh[t + s]);
        __syncthreads();
    }
    float mx = sh[0];
    __syncthreads();
    float e = __expf(p - mx);
    sh[t] = e;
    __syncthreads();
    #pragma unroll
    for (int s = 256; s > 0; s >>= 1) {
        if (t < s) sh[t] += sh[t + s];
        __syncthreads();
    }
    g_w[t] = e * (1.0f / sh[0]);

    // ||c||^2 for center t
    const float4* c4 = (const float4*)(centers + (size_t)t * DD);
    float s2 = 0.f;
    #pragma unroll
    for (int i = 0; i < DD / 4; i++) {
        float4 v = c4[i];
        s2 += v.x * v.x + v.y * v.y + v.z * v.z + v.w * v.w;
    }
    g_c2[t] = s2;
}

// ---------------------------------------------------------------------------
// Main: 128x512 (rows x centers) per CTA, fused dist2 -> exp -> weighted sum.
// ---------------------------------------------------------------------------
__global__ void __launch_bounds__(NTHREADS, 2)
main_kernel(const float* __restrict__ F,       // (B*N, 64) row-major
            const float* __restrict__ C,       // (KC, 64)  row-major
            const float* __restrict__ betap) {
    __shared__ float As[DD][TM + PAD];
    __shared__ float Bs[DD][TN + PAD];
    __shared__ float f2s[TM];
    __shared__ float red[NTHREADS];

    const int tid = threadIdx.x;
    const int tx  = tid & 15;      // center-tile column group
    const int ty  = tid >> 4;      // row group
    const int row0 = blockIdx.x * TM;
    const float nbeta = -(*betap);

    // ---- stage A tile (TM x 64), transposed into As[k][row] ----
    {
        const float4* Fv = (const float4*)(F + (size_t)row0 * DD);
        #pragma unroll
        for (int i = 0; i < (TM * DD / 4) / NTHREADS; i++) {
            int f  = tid + i * NTHREADS;
            int r  = f >> 4;
            int c4 = f & 15;
            float4 v = Fv[f];
            As[c4 * 4 + 0][r] = v.x;
            As[c4 * 4 + 1][r] = v.y;
            As[c4 * 4 + 2][r] = v.z;
            As[c4 * 4 + 3][r] = v.w;
        }
    }
    __syncthreads();

    // ---- ||f||^2 per row ----
    if (tid < TM) {
        float s = 0.f;
        #pragma unroll
        for (int k = 0; k < DD; k++) {
            float a = As[k][tid];
            s = fmaf(a, a, s);
        }
        f2s[tid] = s;
    }

    float score = 0.f;

    for (int ct = 0; ct < KC / TN; ct++) {
        __syncthreads();   // previous Bs readers done (also covers f2s on ct==0)
        // ---- stage B tile (TN centers x 64), transposed ----
        {
            const float4* Cv = (const float4*)(C + (size_t)ct * TN * DD);
            #pragma unroll
            for (int i = 0; i < (TN * DD / 4) / NTHREADS; i++) {
                int f  = tid + i * NTHREADS;
                int r  = f >> 4;
                int c4 = f & 15;
                float4 v = Cv[f];
                Bs[c4 * 4 + 0][r] = v.x;
                Bs[c4 * 4 + 1][r] = v.y;
                Bs[c4 * 4 + 2][r] = v.z;
                Bs[c4 * 4 + 3][r] = v.w;
            }
        }
        __syncthreads();

        // ---- 8x8 register tile over K=64 ----
        float acc[8][8];
        #pragma unroll
        for (int i = 0; i < 8; i++)
            #pragma unroll
            for (int j = 0; j < 8; j++) acc[i][j] = 0.f;

        #pragma unroll 8
        for (int k = 0; k < DD; k++) {
            float4 a0 = *(const float4*)&As[k][ty * 8];
            float4 a1 = *(const float4*)&As[k][ty * 8 + 4];
            float4 b0 = *(const float4*)&Bs[k][tx * 8];
            float4 b1 = *(const float4*)&Bs[k][tx * 8 + 4];
            float a[8] = {a0.x, a0.y, a0.z, a0.w, a1.x, a1.y, a1.z, a1.w};
            float b[8] = {b0.x, b0.y, b0.z, b0.w, b1.x, b1.y, b1.z, b1.w};
            #pragma unroll
            for (int i = 0; i < 8; i++)
                #pragma unroll
                for (int j = 0; j < 8; j++)
                    acc[i][j] = fmaf(a[i], b[j], acc[i][j]);
        }

        // ---- fused epilogue: dist2 -> exp -> weighted accumulate ----
        const int cb = ct * TN + tx * 8;
        float c2r[8], wr[8];
        #pragma unroll
        for (int j = 0; j < 8; j++) { c2r[j] = g_c2[cb + j]; wr[j] = g_w[cb + j]; }

        #pragma unroll
        for (int i = 0; i < 8; i++) {
            const float f2 = f2s[ty * 8 + i];
            #pragma unroll
            for (int j = 0; j < 8; j++) {
                float d2 = fmaf(-2.0f, acc[i][j], f2 + c2r[j]);
                d2 = fmaxf(d2, 0.0f);
                score = fmaf(wr[j], __expf(nbeta * d2), score);
            }
        }
    }

    // ---- deterministic block reduction ----
    red[tid] = score;
    __syncthreads();
    #pragma unroll
    for (int s = NTHREADS / 2; s > 0; s >>= 1) {
        if (tid < s) red[tid] += red[tid + s];
        __syncthreads();
    }
    if (tid == 0) g_part[blockIdx.x] = red[0];
}

// ---------------------------------------------------------------------------
// Final: deterministic per-batch reduction of CTA partials, scale by 1/N.
// ---------------------------------------------------------------------------
__global__ void final_kernel(float* __restrict__ out) {
    int b = threadIdx.x;   // 0..63
    const int per_b = NBLOCKS / BB;   // 16 CTAs per batch element
    float s = 0.f;
    #pragma unroll
    for (int i = 0; i < per_b; i++) s += g_part[b * per_b + i];
    out[b] = s * (1.0f / NN);
}

// ---------------------------------------------------------------------------
extern "C" void kernel_launch(void* const* d_in, const int* in_sizes, int n_in,
                              void* d_out, int out_size) {
    const float* F       = (const float*)d_in[0];   // (64, 2048, 64) f32
    const float* centers = (const float*)d_in[1];   // (512, 64)      f32
    const float* psi     = (const float*)d_in[2];   // (512,)         f32
    const float* beta    = (const float*)d_in[3];   // scalar         f32
    float* out           = (float*)d_out;           // (64,)          f32

    prep_kernel<<<1, KC>>>(psi, centers);
    main_kernel<<<NBLOCKS, NTHREADS>>>(F, centers, beta);
    final_kernel<<<1, BB>>>(out);
}

// round 3
// speedup vs baseline: 2.7470x; 2.7470x over previous
#include <cuda_runtime.h>
#include <cuda_bf16.h>
#include <cstdint>

#define KC    512
#define DD    64
#define NN    2048
#define BB    64
#define TM    128
#define NTILES 1024          // (BB*NN)/TM
#define NTHREADS 256
#define GRID  148
#define L2E   1.4426950408889634f

// ---------------- smem layout (dynamic) ----------------
#define SMEM_AH   0          // 128 rows x 128B bf16 hi (16KB)
#define SMEM_AL   16384      // 16KB
#define SMEM_BH   32768      // 512 rows x 128B bf16 hi (64KB)
#define SMEM_BL   98304      // 64KB
#define SMEM_CW   163840     // float2[512] (l2nb*c2, w) 4KB
#define SMEM_F2P  167936     // float[1024] partials 4KB
#define SMEM_F2S  172032     // float[128]
#define SMEM_RED  172544     // float[256] 1KB
#define SMEM_TOTAL 173568

__device__ float g_part[NTILES];

// ---------------- helpers ----------------
__device__ __forceinline__ uint32_t smem_u32(const void* p) {
    uint32_t a;
    asm("{ .reg .u64 t; cvta.to.shared.u64 t, %1; cvt.u32.u64 %0, t; }" : "=r"(a) : "l"(p));
    return a;
}
__device__ __forceinline__ float ex2f(float x) {
    float r; asm("ex2.approx.ftz.f32 %0, %1;" : "=f"(r) : "f"(x)); return r;
}
#define SWZ128(off) ((off) ^ (((off) >> 3) & 0x70))

__device__ __forceinline__ void ldsm4(uint32_t addr, uint32_t* r) {
    asm volatile("ldmatrix.sync.aligned.m8n8.x4.shared.b16 {%0,%1,%2,%3}, [%4];"
        : "=r"(r[0]), "=r"(r[1]), "=r"(r[2]), "=r"(r[3]) : "r"(addr));
}
__device__ __forceinline__ void mma_bf16(float* c, const uint32_t* a, const uint32_t* b) {
    asm volatile(
        "mma.sync.aligned.m16n8k16.row.col.f32.bf16.bf16.f32 "
        "{%0,%1,%2,%3}, {%4,%5,%6,%7}, {%8,%9}, {%0,%1,%2,%3};"
        : "+f"(c[0]), "+f"(c[1]), "+f"(c[2]), "+f"(c[3])
        : "r"(a[0]), "r"(a[1]), "r"(a[2]), "r"(a[3]), "r"(b[0]), "r"(b[1]));
}

// split 8 floats -> (hi bf16, lo bf16) packed pairwise; ss = sum of squares
__device__ __forceinline__ void split8(const float* v, uint4& hi, uint4& lo, float& ss) {
    float r[8]; __nv_bfloat16 h[8];
    ss = 0.f;
#pragma unroll
    for (int i = 0; i < 8; i++) {
        float a = v[i];
        ss = fmaf(a, a, ss);
        h[i] = __float2bfloat16(a);
        r[i] = a - __bfloat162float(h[i]);
    }
    uint32_t* hp = (uint32_t*)&hi;
    uint32_t* lp = (uint32_t*)&lo;
#pragma unroll
    for (int i = 0; i < 4; i++) {
        __nv_bfloat162 th = __nv_bfloat162(h[2*i], h[2*i+1]);
        __nv_bfloat162 tl = __floats2bfloat162_rn(r[2*i], r[2*i+1]);
        hp[i] = *(uint32_t*)&th;
        lp[i] = *(uint32_t*)&tl;
    }
}

// ---------------------------------------------------------------------------
__global__ void __launch_bounds__(NTHREADS, 1)
main_kernel(const float* __restrict__ F,
            const float* __restrict__ C,
            const float* __restrict__ psi,
            const float* __restrict__ betap) {
    extern __shared__ __align__(1024) char smem[];
    const uint32_t sb = smem_u32(smem);
    const int tid  = threadIdx.x;
    const int lane = tid & 31;
    const int wid  = tid >> 5;

    float*  red = (float*)(smem + SMEM_RED);
    float2* cw  = (float2*)(smem + SMEM_CW);
    float*  f2p = (float*)(smem + SMEM_F2P);
    float*  f2s = (float*)(smem + SMEM_F2S);

    const float beta = *betap;
    const float l2nb = -beta * L2E;          // < 0
    const float coef = -2.0f * l2nb;         // = 2*beta*log2e > 0

    // ---- softmax(psi) ----
    float p0 = psi[tid], p1 = psi[tid + 256];
    red[tid] = fmaxf(p0, p1);
    __syncthreads();
#pragma unroll
    for (int s = 128; s > 0; s >>= 1) {
        if (tid < s) red[tid] = fmaxf(red[tid], red[tid + s]);
        __syncthreads();
    }
    float mx = red[0];
    __syncthreads();
    float e0 = ex2f((p0 - mx) * L2E), e1 = ex2f((p1 - mx) * L2E);
    f2p[tid] = e0; f2p[tid + 256] = e1;
    red[tid] = e0 + e1;
    __syncthreads();
#pragma unroll
    for (int s = 128; s > 0; s >>= 1) {
        if (tid < s) red[tid] += red[tid + s];
        __syncthreads();
    }
    float rden = 1.0f / red[0];

    // ---- convert centers -> Bh/Bl (SW128 per 128B row), c2 partials ----
    float* c2p = (float*)(smem + SMEM_AH);   // A region as scratch
    for (int i = tid; i < KC * 8; i += NTHREADS) {
        int r = i >> 3, ck = i & 7;
        float v[8];
        const float4* src = (const float4*)(C + (size_t)r * DD + ck * 8);
        *(float4*)&v[0] = src[0];
        *(float4*)&v[4] = src[1];
        uint4 hi, lo; float ss;
        split8(v, hi, lo, ss);
        c2p[i] = ss;
        uint32_t sw = SWZ128((uint32_t)(r * 128 + ck * 16));
        *(uint4*)(smem + SMEM_BH + sw) = hi;
        *(uint4*)(smem + SMEM_BL + sw) = lo;
    }
    __syncthreads();
    for (int j = tid; j < KC; j += NTHREADS) {
        float s = 0.f;
#pragma unroll
        for (int k = 0; k < 8; k++) s += c2p[j * 8 + k];
        cw[j] = make_float2(l2nb * s, f2p[j] * rden);
    }
    __syncthreads();

    // ---- per-warp ldmatrix lane addressing (canonical x4 mapping) ----
    const int rb  = (wid & 3) * 32;          // 32-row block
    const int cb0 = (wid >> 2) * 256;        // 256-col half
    const int arow = lane & 15;
    const uint32_t alx = (uint32_t)(((lane >> 4) * 16) ^ ((arow & 7) * 16));
    const uint32_t abase0 = sb + SMEM_AH + (uint32_t)(rb + arow) * 128;
    const int bg = lane >> 3, br = lane & 7;
    const uint32_t blx = (uint32_t)(((bg & 1) * 16) ^ (br * 16));
    const int bnoff = br + (bg >> 1) * 8;

    // ================= tile loop (persistent) =================
#pragma unroll 1
    for (int t = blockIdx.x; t < NTILES; t += GRID) {
        const size_t row0 = (size_t)t * TM;

        // ---- convert A tile -> Ah/Al + f2 partials ----
        for (int i = tid; i < TM * 8; i += NTHREADS) {
            int r = i >> 3, ck = i & 7;
            float v[8];
            const float4* src = (const float4*)(F + (row0 + r) * DD + ck * 8);
            *(float4*)&v[0] = src[0];
            *(float4*)&v[4] = src[1];
            uint4 hi, lo; float ss;
            split8(v, hi, lo, ss);
            f2p[i] = ss;
            uint32_t sw = SWZ128((uint32_t)(r * 128 + ck * 16));
            *(uint4*)(smem + SMEM_AH + sw) = hi;
            *(uint4*)(smem + SMEM_AL + sw) = lo;
        }
        __syncthreads();
        if (tid < TM) {
            float s = 0.f;
#pragma unroll
            for (int k = 0; k < 8; k++) s += f2p[tid * 8 + k];
            f2s[tid] = l2nb * s;
        }
        __syncthreads();

        float score = 0.f;

#pragma unroll 1
        for (int nc = 0; nc < 4; nc++) {
            const int cb = cb0 + nc * 64;
            uint32_t bbase[4];
#pragma unroll
            for (int np = 0; np < 4; np++)
                bbase[np] = sb + SMEM_BH + (uint32_t)(cb + np * 16 + bnoff) * 128;

            float acc[2][8][4];
#pragma unroll
            for (int mt = 0; mt < 2; mt++)
#pragma unroll
                for (int nt = 0; nt < 8; nt++)
#pragma unroll
                    for (int q = 0; q < 4; q++) acc[mt][nt][q] = 0.f;

#pragma unroll
            for (int kt = 0; kt < 4; kt++) {
                const uint32_t ka = ((uint32_t)(kt * 32)) ^ alx;
                const uint32_t kb = ((uint32_t)(kt * 32)) ^ blx;
                uint32_t ah[2][4], alr[2][4], bh[4][4], blr[4][4];
#pragma unroll
                for (int mt = 0; mt < 2; mt++) {
                    ldsm4(abase0 + mt * 2048 + ka,         ah[mt]);
                    ldsm4(abase0 + mt * 2048 + ka + 16384, alr[mt]);
                }
#pragma unroll
                for (int np = 0; np < 4; np++) {
                    ldsm4(bbase[np] + kb,         bh[np]);
                    ldsm4(bbase[np] + kb + 65536, blr[np]);
                }
#pragma unroll
                for (int mt = 0; mt < 2; mt++)
#pragma unroll
                    for (int np = 0; np < 4; np++)
#pragma unroll
                        for (int h = 0; h < 2; h++) {
                            float* acp = acc[mt][np * 2 + h];
                            mma_bf16(acp, ah[mt],  &bh[np][h * 2]);
                            mma_bf16(acp, ah[mt],  &blr[np][h * 2]);
                            mma_bf16(acp, alr[mt], &bh[np][h * 2]);
                        }
            }

            // ---- fused epilogue on register fragments ----
            const int ccol = cb + 2 * (lane & 3);
#pragma unroll
            for (int mt = 0; mt < 2; mt++) {
                const int r0 = rb + mt * 16 + (lane >> 2);
                const float f20 = f2s[r0], f21 = f2s[r0 + 8];
#pragma unroll
                for (int nt = 0; nt < 8; nt++) {
                    const float4 cwv = *(const float4*)(cw + ccol + nt * 8);
                    const float* a = acc[mt][nt];
                    float g0 = fminf(fmaf(coef, a[0], f20 + cwv.x), 0.f);
                    float g1 = fminf(fmaf(coef, a[1], f20 + cwv.z), 0.f);
                    float g2 = fminf(fmaf(coef, a[2], f21 + cwv.x), 0.f);
                    float g3 = fminf(fmaf(coef, a[3], f21 + cwv.z), 0.f);
                    score = fmaf(cwv.y, ex2f(g0), score);
                    score = fmaf(cwv.w, ex2f(g1), score);
                    score = fmaf(cwv.y, ex2f(g2), score);
                    score = fmaf(cwv.w, ex2f(g3), score);
                }
            }
        }

        // ---- deterministic block reduction ----
        red[tid] = score;
        __syncthreads();
#pragma unroll
        for (int s = NTHREADS / 2; s > 0; s >>= 1) {
            if (tid < s) red[tid] += red[tid + s];
            __syncthreads();
        }
        if (tid == 0) g_part[t] = red[0];
        __syncthreads();
    }
}

// ---------------------------------------------------------------------------
__global__ void final_kernel(float* __restrict__ out) {
    int b = threadIdx.x;                 // 0..63
    const int per_b = NTILES / BB;       // 16
    float s = 0.f;
#pragma unroll
    for (int i = 0; i < per_b; i++) s += g_part[b * per_b + i];
    out[b] = s * (1.0f / NN);
}

// ---------------------------------------------------------------------------
extern "C" void kernel_launch(void* const* d_in, const int* in_sizes, int n_in,
                              void* d_out, int out_size) {
    const float* F       = (const float*)d_in[0];
    const float* centers = (const float*)d_in[1];
    const float* psi     = (const float*)d_in[2];
    const float* beta    = (const float*)d_in[3];
    float* out           = (float*)d_out;

    cudaFuncSetAttribute(main_kernel, cudaFuncAttributeMaxDynamicSharedMemorySize, SMEM_TOTAL);
    main_kernel<<<GRID, NTHREADS, SMEM_TOTAL>>>(F, centers, psi, beta);
    final_kernel<<<1, BB>>>(out);
}

// round 4
// speedup vs baseline: 2.9069x; 1.0582x over previous
#include <cuda_runtime.h>
#include <cuda_bf16.h>
#include <cstdint>

#define KC    512
#define DD    64
#define NN    2048
#define BB    64
#define TM    128
#define NTILES 1024          // (BB*NN)/TM
#define NTHREADS 256
#define GRID  148
#define L2E   1.4426950408889634f

// ---------------- smem layout (dynamic) ----------------
#define SMEM_AH   0          // 128 rows x 128B bf16 hi (16KB)
#define SMEM_AL   16384      // 16KB
#define SMEM_BH   32768      // 512 rows x 128B bf16 hi (64KB)
#define SMEM_BL   98304      // 64KB
#define SMEM_CW   163840     // float2[512] (l2nb*c2, w) 4KB
#define SMEM_F2P  167936     // float[1024] partials 4KB
#define SMEM_F2S  172032     // float[128]
#define SMEM_RED  172544     // float[8] + int flag
#define SMEM_TOTAL 172608

__device__ float g_part[NTILES];
__device__ int   g_count;    // zero-init; self-resets each launch

// ---------------- helpers ----------------
__device__ __forceinline__ uint32_t smem_u32(const void* p) {
    uint32_t a;
    asm("{ .reg .u64 t; cvta.to.shared.u64 t, %1; cvt.u32.u64 %0, t; }" : "=r"(a) : "l"(p));
    return a;
}
__device__ __forceinline__ float ex2f(float x) {
    float r; asm("ex2.approx.ftz.f32 %0, %1;" : "=f"(r) : "f"(x)); return r;
}
#define SWZ128(off) ((off) ^ (((off) >> 3) & 0x70))

__device__ __forceinline__ void ldsm4(uint32_t addr, uint32_t* r) {
    asm volatile("ldmatrix.sync.aligned.m8n8.x4.shared.b16 {%0,%1,%2,%3}, [%4];"
        : "=r"(r[0]), "=r"(r[1]), "=r"(r[2]), "=r"(r[3]) : "r"(addr));
}
__device__ __forceinline__ void mma_bf16(float* c, const uint32_t* a, const uint32_t* b) {
    asm volatile(
        "mma.sync.aligned.m16n8k16.row.col.f32.bf16.bf16.f32 "
        "{%0,%1,%2,%3}, {%4,%5,%6,%7}, {%8,%9}, {%0,%1,%2,%3};"
        : "+f"(c[0]), "+f"(c[1]), "+f"(c[2]), "+f"(c[3])
        : "r"(a[0]), "r"(a[1]), "r"(a[2]), "r"(a[3]), "r"(b[0]), "r"(b[1]));
}

// split 8 floats -> (hi bf16, lo bf16) packed pairwise; ss = sum of squares
__device__ __forceinline__ void split8(const float* v, uint4& hi, uint4& lo, float& ss) {
    float r[8]; __nv_bfloat16 h[8];
    ss = 0.f;
#pragma unroll
    for (int i = 0; i < 8; i++) {
        float a = v[i];
        ss = fmaf(a, a, ss);
        h[i] = __float2bfloat16(a);
        r[i] = a - __bfloat162float(h[i]);
    }
    uint32_t* hp = (uint32_t*)&hi;
    uint32_t* lp = (uint32_t*)&lo;
#pragma unroll
    for (int i = 0; i < 4; i++) {
        __nv_bfloat162 th = __nv_bfloat162(h[2*i], h[2*i+1]);
        __nv_bfloat162 tl = __floats2bfloat162_rn(r[2*i], r[2*i+1]);
        hp[i] = *(uint32_t*)&th;
        lp[i] = *(uint32_t*)&tl;
    }
}

// ---------------------------------------------------------------------------
__global__ void __launch_bounds__(NTHREADS, 1)
main_kernel(const float* __restrict__ F,
            const float* __restrict__ C,
            const float* __restrict__ psi,
            const float* __restrict__ betap,
            float* __restrict__ out) {
    extern __shared__ __align__(1024) char smem[];
    const uint32_t sb = smem_u32(smem);
    const int tid  = threadIdx.x;
    const int lane = tid & 31;
    const int wid  = tid >> 5;

    float*  red = (float*)(smem + SMEM_RED);
    int*    flg = (int*)(smem + SMEM_RED + 32);
    float2* cw  = (float2*)(smem + SMEM_CW);
    float*  f2p = (float*)(smem + SMEM_F2P);
    float*  f2s = (float*)(smem + SMEM_F2S);

    const float beta = *betap;
    const float l2nb = -beta * L2E;          // < 0
    const float coef = -2.0f * l2nb;         // > 0

    // ---- prefetch first A tile into registers (latency hidden by setup) ----
    float4 pf[8];
    {
        const float4* src = (const float4*)(F + (size_t)blockIdx.x * TM * DD);
#pragma unroll
        for (int k = 0; k < 4; k++) {
            int i = tid + k * NTHREADS;
            pf[2*k]   = src[2*i];
            pf[2*k+1] = src[2*i+1];
        }
    }

    // ---- softmax(psi) (reuse f2p region for e-values) ----
    float p0 = psi[tid], p1 = psi[tid + 256];
    {
        float* rtmp = f2p;   // 256 floats scratch (f2p is 1024 floats)
        rtmp[tid] = fmaxf(p0, p1);
        __syncthreads();
#pragma unroll
        for (int s = 128; s > 0; s >>= 1) {
            if (tid < s) rtmp[tid] = fmaxf(rtmp[tid], rtmp[tid + s]);
            __syncthreads();
        }
        float mx = rtmp[0];
        __syncthreads();
        float e0 = ex2f((p0 - mx) * L2E), e1 = ex2f((p1 - mx) * L2E);
        float* ews = f2p + 256;              // won't collide with rtmp[0..255]? yes it does at 256.. use cw region later
        // store e-values into upper half of f2p scratch region temporarily
        ews[tid] = e0; ews[tid + 256] = e1;  // f2p[256..767]
        rtmp[tid] = e0 + e1;
        __syncthreads();
#pragma unroll
        for (int s = 128; s > 0; s >>= 1) {
            if (tid < s) rtmp[tid] += rtmp[tid + s];
            __syncthreads();
        }
        float rden = 1.0f / rtmp[0];
        __syncthreads();

        // ---- convert centers -> Bh/Bl (SW128), c2 partials in A region ----
        float* c2p = (float*)(smem + SMEM_AH);   // 4096 floats scratch
        for (int i = tid; i < KC * 8; i += NTHREADS) {
            int r = i >> 3, ck = i & 7;
            float v[8];
            const float4* src = (const float4*)(C + (size_t)r * DD + ck * 8);
            *(float4*)&v[0] = src[0];
            *(float4*)&v[4] = src[1];
            uint4 hi, lo; float ss;
            split8(v, hi, lo, ss);
            c2p[i] = ss;
            uint32_t sw = SWZ128((uint32_t)(r * 128 + ck * 16));
            *(uint4*)(smem + SMEM_BH + sw) = hi;
            *(uint4*)(smem + SMEM_BL + sw) = lo;
        }
        __syncthreads();
        for (int j = tid; j < KC; j += NTHREADS) {
            float s = 0.f;
#pragma unroll
            for (int k = 0; k < 8; k++) s += c2p[j * 8 + k];
            cw[j] = make_float2(l2nb * s, ews[j] * rden);
        }
        __syncthreads();
    }

    // ---- convert first A tile (pf regs) into smem + f2 partials ----
#pragma unroll
    for (int k = 0; k < 4; k++) {
        int i = tid + k * NTHREADS;
        int r = i >> 3, ck = i & 7;
        float v[8];
        *(float4*)&v[0] = pf[2*k];
        *(float4*)&v[4] = pf[2*k+1];
        uint4 hi, lo; float ss;
        split8(v, hi, lo, ss);
        f2p[i] = ss;
        uint32_t sw = SWZ128((uint32_t)(r * 128 + ck * 16));
        *(uint4*)(smem + SMEM_AH + sw) = hi;
        *(uint4*)(smem + SMEM_AL + sw) = lo;
    }

    // ---- per-warp ldmatrix lane addressing ----
    const int rb  = (wid & 3) * 32;          // 32-row block
    const int cb0 = (wid >> 2) * 256;        // 256-col half
    const int ncrot = (wid & 1) << 1;        // anti-phase chunk rotation
    const int arow = lane & 15;
    const uint32_t alx = (uint32_t)(((lane >> 4) * 16) ^ ((arow & 7) * 16));
    const uint32_t abase0 = sb + SMEM_AH + (uint32_t)(rb + arow) * 128;
    const int bg = lane >> 3, br = lane & 7;
    const uint32_t blx = (uint32_t)(((bg & 1) * 16) ^ (br * 16));
    const int bnoff = br + (bg >> 1) * 8;

    // ================= tile loop (persistent) =================
#pragma unroll 1
    for (int t = blockIdx.x; t < NTILES; t += GRID) {
        __syncthreads();   // S1: A(t) + f2p(t) stores visible

        const bool havepf = (t + GRID < NTILES);
        if (havepf) {
            const float4* src = (const float4*)(F + (size_t)(t + GRID) * TM * DD);
#pragma unroll
            for (int k = 0; k < 4; k++) {
                int i = tid + k * NTHREADS;
                pf[2*k]   = src[2*i];
                pf[2*k+1] = src[2*i+1];
            }
        }

        if (tid < TM) {
            float s = 0.f;
#pragma unroll
            for (int k = 0; k < 8; k++) s += f2p[tid * 8 + k];
            f2s[tid] = l2nb * s;
        }
        __syncthreads();   // S1b: f2s visible

        float score = 0.f;

#pragma unroll 1
        for (int ncit = 0; ncit < 4; ncit++) {
            const int nc = (ncit + ncrot) & 3;
            const int cb = cb0 + nc * 64;
            uint32_t bbase[4];
#pragma unroll
            for (int np = 0; np < 4; np++)
                bbase[np] = sb + SMEM_BH + (uint32_t)(cb + np * 16 + bnoff) * 128;

            float acc[2][8][4];
#pragma unroll
            for (int mt = 0; mt < 2; mt++)
#pragma unroll
                for (int nt = 0; nt < 8; nt++)
#pragma unroll
                    for (int q = 0; q < 4; q++) acc[mt][nt][q] = 0.f;

#pragma unroll
            for (int kt = 0; kt < 4; kt++) {
                const uint32_t ka = ((uint32_t)(kt * 32)) ^ alx;
                const uint32_t kb = ((uint32_t)(kt * 32)) ^ blx;
                uint32_t ah[2][4], alr[2][4], bh[4][4], blr[4][4];
#pragma unroll
                for (int mt = 0; mt < 2; mt++) {
                    ldsm4(abase0 + mt * 2048 + ka,         ah[mt]);
                    ldsm4(abase0 + mt * 2048 + ka + 16384, alr[mt]);
                }
#pragma unroll
                for (int np = 0; np < 4; np++) {
                    ldsm4(bbase[np] + kb,         bh[np]);
                    ldsm4(bbase[np] + kb + 65536, blr[np]);
                }
#pragma unroll
                for (int mt = 0; mt < 2; mt++)
#pragma unroll
                    for (int np = 0; np < 4; np++)
#pragma unroll
                        for (int h = 0; h < 2; h++) {
                            float* acp = acc[mt][np * 2 + h];
                            mma_bf16(acp, ah[mt],  &bh[np][h * 2]);
                            mma_bf16(acp, ah[mt],  &blr[np][h * 2]);
                            mma_bf16(acp, alr[mt], &bh[np][h * 2]);
                        }
            }

            // ---- fused epilogue on register fragments ----
            const int ccol = cb + 2 * (lane & 3);
#pragma unroll
            for (int mt = 0; mt < 2; mt++) {
                const int r0 = rb + mt * 16 + (lane >> 2);
                const float f20 = f2s[r0], f21 = f2s[r0 + 8];
#pragma unroll
                for (int nt = 0; nt < 8; nt++) {
                    const float4 cwv = *(const float4*)(cw + ccol + nt * 8);
                    const float* a = acc[mt][nt];
                    float g0 = fminf(fmaf(coef, a[0], f20 + cwv.x), 0.f);
                    float g1 = fminf(fmaf(coef, a[1], f20 + cwv.z), 0.f);
                    float g2 = fminf(fmaf(coef, a[2], f21 + cwv.x), 0.f);
                    float g3 = fminf(fmaf(coef, a[3], f21 + cwv.z), 0.f);
                    score = fmaf(cwv.y, ex2f(g0), score);
                    score = fmaf(cwv.w, ex2f(g1), score);
                    score = fmaf(cwv.y, ex2f(g2), score);
                    score = fmaf(cwv.w, ex2f(g3), score);
                }
            }
        }

        // ---- shuffle reduction ----
#pragma unroll
        for (int o = 16; o > 0; o >>= 1)
            score += __shfl_xor_sync(0xFFFFFFFFu, score, o);
        if (lane == 0) red[wid] = score;
        __syncthreads();   // S2: all warps done with A/f2s; red ready
        if (tid == 0) {
            float s = 0.f;
#pragma unroll
            for (int w = 0; w < 8; w++) s += red[w];
            g_part[t] = s;
        }

        // ---- convert next A tile from pf regs (overwrites A region) ----
        if (havepf) {
#pragma unroll
            for (int k = 0; k < 4; k++) {
                int i = tid + k * NTHREADS;
                int r = i >> 3, ck = i & 7;
                float v[8];
                *(float4*)&v[0] = pf[2*k];
                *(float4*)&v[4] = pf[2*k+1];
                uint4 hi, lo; float ss;
                split8(v, hi, lo, ss);
                f2p[i] = ss;
                uint32_t sw = SWZ128((uint32_t)(r * 128 + ck * 16));
                *(uint4*)(smem + SMEM_AH + sw) = hi;
                *(uint4*)(smem + SMEM_AL + sw) = lo;
            }
        }
    }

    // ---- last CTA reduces partials into out ----
    __threadfence();
    if (tid == 0) {
        int p = atomicAdd(&g_count, 1);
        *flg = (p == GRID - 1);
    }
    __syncthreads();
    if (*flg) {
        __threadfence();
        if (tid < BB) {
            float s = 0.f;
#pragma unroll
            for (int i = 0; i < NTILES / BB; i++) s += g_part[tid * (NTILES / BB) + i];
            out[tid] = s * (1.0f / NN);
        }
        if (tid == 0) g_count = 0;   // reset for next graph replay
    }
}

// ---------------------------------------------------------------------------
extern "C" void kernel_launch(void* const* d_in, const int* in_sizes, int n_in,
                              void* d_out, int out_size) {
    const float* F       = (const float*)d_in[0];
    const float* centers = (const float*)d_in[1];
    const float* psi     = (const float*)d_in[2];
    const float* beta    = (const float*)d_in[3];
    float* out           = (float*)d_out;

    cudaFuncSetAttribute(main_kernel, cudaFuncAttributeMaxDynamicSharedMemorySize, SMEM_TOTAL);
    main_kernel<<<GRID, NTHREADS, SMEM_TOTAL>>>(F, centers, psi, beta, out);
}